// round 1
// baseline (speedup 1.0000x reference)
#include <cuda_runtime.h>

// Problem constants (fixed by setup_inputs)
#define NB        64            // batch
#define SD        52            // grid S
#define CELLS     (SD * SD)     // 2704 = 169 * 16
#define BX        3             // boxes
#define CH        255           // (5+80)*3 channels per cell
#define CPB       16            // cells per block (2704 % 16 == 0)
#define THREADS   128
#define TPC       8             // threads per cell
#define EPSF      1e-6f
#define IOU_T     0.7f
#define SCALE_IDX 2             // SCALES.index(52/13) = index of 4.0

__global__ void zero_out_kernel(float* out) {
    int t = threadIdx.x;
    if (t < 257) out[t] = 0.0f;
}

__device__ __forceinline__ float warp_sum(float v) {
    #pragma unroll
    for (int o = 16; o > 0; o >>= 1) v += __shfl_down_sync(0xffffffffu, v, o);
    return v;
}

__global__ __launch_bounds__(THREADS) void yolo_loss_kernel(
    const float* __restrict__ yhat,
    const float* __restrict__ ytru,
    const float* __restrict__ anchors,
    float* __restrict__ out)
{
    __shared__ float shH[CPB * CH];
    __shared__ float shY[CPB * CH];
    __shared__ float red[4][4];

    const int n     = blockIdx.y;
    const int cell0 = blockIdx.x * CPB;
    const size_t base = ((size_t)n * CELLS + cell0) * CH;   // 16B-aligned in bytes

    // ---- Stage tile: 16 cells x 255 ch x 2 tensors, coalesced float4 ----
    const float4* srcH = reinterpret_cast<const float4*>(yhat + base);
    const float4* srcY = reinterpret_cast<const float4*>(ytru + base);
    float4* dH = reinterpret_cast<float4*>(shH);
    float4* dY = reinterpret_cast<float4*>(shY);
    const int NF4 = CPB * CH / 4;  // 1020 exact
    #pragma unroll
    for (int i = threadIdx.x; i < NF4; i += THREADS) {
        dH[i] = srcH[i];
        dY[i] = srcY[i];
    }
    __syncthreads();

    // ---- Per-cell compute: 8 threads per cell ----
    const int lc  = threadIdx.x / TPC;   // local cell 0..15
    const int sub = threadIdx.x % TPC;   // 0..7
    const int cellIdx = cell0 + lc;
    const int gi = cellIdx / SD;         // row (i)
    const int gj = cellIdx % SD;         // col (j)

    const float* H = shH + lc * CH;
    const float* Y = shY + lc * CH;

    // Box fields
    float hx[BX], hy[BX], hw[BX], hh[BX], hc[BX];
    float yx[BX], yy[BX], yw[BX], yh[BX], yc[BX];
    #pragma unroll
    for (int b = 0; b < BX; b++) {
        const float* hb = H + b * 85;
        const float* yb = Y + b * 85;
        hx[b] = hb[0]; hy[b] = hb[1]; hw[b] = hb[2]; hh[b] = hb[3]; hc[b] = hb[4];
        yx[b] = yb[0]; yy[b] = yb[1]; yw[b] = yb[2]; yh[b] = yb[3]; yc[b] = yb[4];
    }

    const float invS = 1.0f / (float)SD;
    const float fj = (float)gj, fi = (float)gi;

    // Corner boxes
    float hx1[BX], hx2[BX], hy1[BX], hy2[BX];
    float tx1[BX], tx2[BX], ty1[BX], ty2[BX];
    #pragma unroll
    for (int b = 0; b < BX; b++) {
        float cx = (hx[b] + fj) * invS, cy = (hy[b] + fi) * invS;
        hx1[b] = cx - 0.5f * hw[b]; hx2[b] = cx + 0.5f * hw[b];
        hy1[b] = cy - 0.5f * hh[b]; hy2[b] = cy + 0.5f * hh[b];
        cx = (yx[b] + fj) * invS; cy = (yy[b] + fi) * invS;
        tx1[b] = cx - 0.5f * yw[b]; tx2[b] = cx + 0.5f * yw[b];
        ty1[b] = cy - 0.5f * yh[b]; ty2[b] = cy + 0.5f * yh[b];
    }

    // IOU matrix: per-pb max (noobj), per-tb argmax (idx).
    int   idx_t[BX];
    float best_t[BX] = {-1.0f, -1.0f, -1.0f};
    float noobj_f[BX];
    #pragma unroll
    for (int pb = 0; pb < BX; pb++) {
        float m = -1.0f;
        #pragma unroll
        for (int tb = 0; tb < BX; tb++) {
            float wi = fminf(hx2[pb], tx2[tb]) - fmaxf(hx1[pb], tx1[tb]);
            float hi = fminf(hy2[pb], ty2[tb]) - fmaxf(hy1[pb], ty1[tb]);
            wi = fmaxf(wi, 0.0f); hi = fmaxf(hi, 0.0f);
            float inter = wi * hi;
            float uni = hw[pb] * hh[pb] + yw[tb] * yh[tb] - inter;
            float iou = inter / (uni + EPSF);
            m = fmaxf(m, iou);
            if (iou > best_t[tb]) { best_t[tb] = iou; idx_t[tb] = pb; }
        }
        noobj_f[pb] = (m < IOU_T) ? 1.0f : 0.0f;
    }

    float coord_acc = 0.0f, cls_acc = 0.0f, noobj_acc = 0.0f, obj_acc = 0.0f;

    if (sub == 0) {
        // anchors for scale_idx
        const float* anc = anchors + SCALE_IDX * BX * 2;
        #pragma unroll
        for (int tb = 0; tb < BX; tb++) {
            int pb = idx_t[tb];
            float ho = (yc[tb] > 0.0f) ? 1.0f : 0.0f;
            float aw_p = __ldg(&anc[pb * 2 + 0]), ah_p = __ldg(&anc[pb * 2 + 1]);
            float aw_t = __ldg(&anc[tb * 2 + 0]), ah_t = __ldg(&anc[tb * 2 + 1]);
            float dx = hx[pb] - yx[tb];
            float dy = hy[pb] - yy[tb];
            float lw_h = __logf(hw[pb] / aw_p + EPSF);
            float lh_h = __logf(hh[pb] / ah_p + EPSF);
            float lw_t = __logf(yw[tb] / aw_t + EPSF);
            float lh_t = __logf(yh[tb] / ah_t + EPSF);
            float dlw = lw_h - lw_t, dlh = lh_h - lh_t;
            float c = dx * dx + dy * dy + dlw * dlw + dlh * dlh;
            c *= ho * (2.0f - yw[tb] * yh[tb]);   // SCALE_COORD
            coord_acc += c;
            float dc = hc[pb] - yc[tb];
            obj_acc += dc * dc * ho;
        }
        #pragma unroll
        for (int pb = 0; pb < BX; pb++)
            noobj_acc += hc[pb] * hc[pb] * noobj_f[pb];   // NO_OBJ_V3 target = 0
    }

    // Class loss: 3 tb x 80 classes, split across 8 threads
    #pragma unroll
    for (int tb = 0; tb < BX; tb++) {
        int pb = idx_t[tb];
        float ho = (yc[tb] > 0.0f) ? 1.0f : 0.0f;
        const float* Hc = H + pb * 85 + 5;
        const float* Yc = Y + tb * 85 + 5;
        float s = 0.0f;
        #pragma unroll
        for (int c = sub; c < 80; c += TPC) {
            float d = Hc[c] - Yc[c];
            s += d * d;
        }
        cls_acc += s * ho;
    }

    // ---- Block reduction (all cells in block share image n) ----
    coord_acc = warp_sum(coord_acc);
    cls_acc   = warp_sum(cls_acc);
    noobj_acc = warp_sum(noobj_acc);
    obj_acc   = warp_sum(obj_acc);

    const int wid = threadIdx.x >> 5;
    if ((threadIdx.x & 31) == 0) {
        red[wid][0] = coord_acc;
        red[wid][1] = cls_acc;
        red[wid][2] = noobj_acc;
        red[wid][3] = obj_acc;
    }
    __syncthreads();
    if (threadIdx.x < 4) {
        float v = red[0][threadIdx.x] + red[1][threadIdx.x] +
                  red[2][threadIdx.x] + red[3][threadIdx.x];
        // layout: coord[0:64) class[64:128) noobj[128:192) obj[192:256) prior[256]
        atomicAdd(out + threadIdx.x * NB + n, v);
    }
}

extern "C" void kernel_launch(void* const* d_in, const int* in_sizes, int n_in,
                              void* d_out, int out_size) {
    const float* yhat    = (const float*)d_in[0];
    const float* y       = (const float*)d_in[1];
    const float* anchors = (const float*)d_in[2];
    float* out = (float*)d_out;

    zero_out_kernel<<<1, 288>>>(out);
    dim3 grid(CELLS / CPB, NB);   // (169, 64)
    yolo_loss_kernel<<<grid, THREADS>>>(yhat, y, anchors, out);
}